// round 8
// baseline (speedup 1.0000x reference)
#include <cuda_runtime.h>
#include <cuda_bf16.h>
#include <math.h>
#include <stdint.h>

#define DIM 512
#define P_MAX 2048
#define R_MAX 65536
#define BM 128
#define BN 256
#define BK 64                  // bf16 elems per chunk = 128 bytes/row
#define NCHUNK (DIM / BK)      // 8
#define STAGES 4
#define NTHREADS 384           // 8 consumer warps + 4 producer warps
#define A_BYTES (BM * 128)     // 16384
#define B_BYTES (BN * 128)     // 32768
#define STAGE_BYTES (A_BYTES + B_BYTES)   // 49152

// SMEM layout
#define SOFF_MBAR 0            // full[4] @ 0..31, empty[4] @ 32..63
#define SOFF_XN   128          // 128 floats
#define SOFF_YN   (SOFF_XN + BM * 4)
#define SOFF_S0   2048         // 1024-aligned stage ring
#define SMEM_BYTES (SOFF_S0 + STAGES * STAGE_BYTES)   // 198656

// Scratch (no allocations allowed)
__device__ __nv_bfloat16 g_A[P_MAX * DIM];   // 2 MB
__device__ __nv_bfloat16 g_B[R_MAX * DIM];   // 64 MB
__device__ float g_xn[P_MAX];
__device__ float g_yn[R_MAX];
__device__ unsigned int g_min_bits;

// ---------------- helpers ----------------
__device__ __forceinline__ unsigned int enc_f(float f) {
    unsigned int u = __float_as_uint(f);
    return (u & 0x80000000u) ? ~u : (u | 0x80000000u);
}
__device__ __forceinline__ float dec_f(unsigned int u) {
    return (u & 0x80000000u) ? __uint_as_float(u & 0x7FFFFFFFu)
                             : __uint_as_float(~u);
}
__device__ __forceinline__ uint32_t smem_u32(const void* p) {
    uint32_t a;
    asm("{ .reg .u64 t; cvta.to.shared.u64 t, %1; cvt.u32.u64 %0, t; }"
        : "=r"(a) : "l"(p));
    return a;
}
__device__ __forceinline__ void cp16(uint32_t dst, const void* src) {
    asm volatile("cp.async.cg.shared.global [%0], [%1], 16;"
                 :: "r"(dst), "l"(src) : "memory");
}
__device__ __forceinline__ uint32_t swz(uint32_t off) {
    return off ^ ((off >> 3) & 0x70);   // SW128 pattern on 128B rows
}
__device__ __forceinline__ void ldsm_x4(uint32_t& r0, uint32_t& r1,
                                        uint32_t& r2, uint32_t& r3,
                                        uint32_t addr) {
    asm volatile("ldmatrix.sync.aligned.m8n8.x4.shared.b16 {%0,%1,%2,%3}, [%4];"
                 : "=r"(r0), "=r"(r1), "=r"(r2), "=r"(r3) : "r"(addr));
}
__device__ __forceinline__ void mma_bf16(float* c, const uint32_t* a,
                                         uint32_t b0, uint32_t b1) {
    asm volatile(
        "mma.sync.aligned.m16n8k16.row.col.f32.bf16.bf16.f32 "
        "{%0,%1,%2,%3}, {%4,%5,%6,%7}, {%8,%9}, {%0,%1,%2,%3};"
        : "+f"(c[0]), "+f"(c[1]), "+f"(c[2]), "+f"(c[3])
        : "r"(a[0]), "r"(a[1]), "r"(a[2]), "r"(a[3]), "r"(b0), "r"(b1));
}
__device__ __forceinline__ void mbar_init(uint32_t mbar, uint32_t cnt) {
    asm volatile("mbarrier.init.shared.b64 [%0], %1;" :: "r"(mbar), "r"(cnt) : "memory");
}
__device__ __forceinline__ void mbar_arrive(uint32_t mbar) {
    asm volatile("mbarrier.arrive.shared.b64 _, [%0];" :: "r"(mbar) : "memory");
}
__device__ __forceinline__ void mbar_wait(uint32_t mbar, int parity) {
    asm volatile(
        "{\n\t.reg .pred P;\n\t"
        "LW%=:\n\t"
        "mbarrier.try_wait.parity.acquire.cta.shared::cta.b64 P, [%0], %1;\n\t"
        "@!P bra LW%=;\n\t}"
        :: "r"(mbar), "r"(parity) : "memory");
}
__device__ __forceinline__ void cpasync_arrive(uint32_t mbar) {
    asm volatile("cp.async.mbarrier.arrive.noinc.shared.b64 [%0];"
                 :: "r"(mbar) : "memory");
}

// ------------- kernel 0: convert to bf16, fp32 norms, reset min -------------
__global__ void prep_kernel(const float* __restrict__ x,
                            const float* __restrict__ y, int P, int R) {
    int warp = (blockIdx.x * blockDim.x + threadIdx.x) >> 5;
    int lane = threadIdx.x & 31;
    if (blockIdx.x == 0 && threadIdx.x == 0) g_min_bits = 0xFFFFFFFFu;
    if (warp >= P + R) return;
    const float4* src4;
    uint2* dst2;
    if (warp < P) {
        src4 = (const float4*)(x + (size_t)warp * DIM);
        dst2 = (uint2*)(g_A + (size_t)warp * DIM);
    } else {
        int r = warp - P;
        src4 = (const float4*)(y + (size_t)r * DIM);
        dst2 = (uint2*)(g_B + (size_t)r * DIM);
    }
    float acc = 0.f;
#pragma unroll
    for (int j = 0; j < 4; j++) {
        float4 v = src4[lane + j * 32];
        acc += v.x * v.x + v.y * v.y + v.z * v.z + v.w * v.w;
        __nv_bfloat162 lo = __floats2bfloat162_rn(v.x, v.y);
        __nv_bfloat162 hi = __floats2bfloat162_rn(v.z, v.w);
        uint2 u;
        u.x = *reinterpret_cast<unsigned int*>(&lo);
        u.y = *reinterpret_cast<unsigned int*>(&hi);
        dst2[lane + j * 32] = u;
    }
#pragma unroll
    for (int off = 16; off > 0; off >>= 1)
        acc += __shfl_xor_sync(0xFFFFFFFFu, acc, off);
    if (lane == 0) {
        if (warp < P) g_xn[warp] = acc;
        else          g_yn[warp - P] = acc;
    }
}

// ------------- kernel 1: warp-specialized bf16 GEMM + min reduction -------------
// CTA tile 128x256. Warps 0-7 consume (64x64 tiles, 2Mx4N); warps 8-11 produce.
__global__ void __launch_bounds__(NTHREADS, 1)
min_dist_mma_kernel(int P, int R) {
    extern __shared__ char smem[];
    uint32_t sbase = smem_u32(smem);
    const int tid = threadIdx.x;
    const int lane = tid & 31;
    const int warp = tid >> 5;
    const int bm = blockIdx.y * BM;
    const int bn = blockIdx.x * BN;

    const uint32_t mb_full = sbase + SOFF_MBAR;        // full[s] = +8*s
    const uint32_t mb_empty = sbase + SOFF_MBAR + 32;  // empty[s] = +8*s

    if (tid == 0) {
#pragma unroll
        for (int s = 0; s < STAGES; s++) {
            mbar_init(mb_full + 8 * s, 128);   // 128 producer threads
            mbar_init(mb_empty + 8 * s, 8);    // 8 consumer warps
        }
    }
    // Stage norms (consumer threads).
    if (tid < 128) ((float*)(smem + SOFF_XN))[tid] = g_xn[bm + tid];
    if (tid < 256) ((float*)(smem + SOFF_YN))[tid] = g_yn[bn + tid];
    __syncthreads();   // only CTA-wide barrier: init + norms visible

    if (warp >= 8) {
        // ---------------- producers ----------------
        const int ptid = tid - 256;   // 0..127
        for (int k = 0; k < NCHUNK; k++) {
            const int s = k & (STAGES - 1);
            if (k >= STAGES)
                mbar_wait(mb_empty + 8 * s, ((k >> 2) - 1) & 1);
            const uint32_t a0 = sbase + SOFF_S0 + s * STAGE_BYTES;
            const uint32_t b0 = a0 + A_BYTES;
            const int k0 = k * BK;
#pragma unroll
            for (int i = 0; i < 8; i++) {            // A: 1024 units / 128 thr
                int u = ptid + i * 128;
                int row = u >> 3, c = u & 7;
                cp16(a0 + swz(row * 128 + c * 16),
                     g_A + (size_t)(bm + row) * DIM + k0 + c * 8);
            }
#pragma unroll
            for (int i = 0; i < 16; i++) {           // B: 2048 units / 128 thr
                int u = ptid + i * 128;
                int row = u >> 3, c = u & 7;
                cp16(b0 + swz(row * 128 + c * 16),
                     g_B + (size_t)(bn + row) * DIM + k0 + c * 8);
            }
            cpasync_arrive(mb_full + 8 * s);   // arrive when this thread's copies land
        }
        return;  // producers done
    }

    // ---------------- consumers ----------------
    const int wm = warp & 1;    // 0..1 : M (64 rows each)
    const int wn = warp >> 1;   // 0..3 : N (64 cols each)

    float acc[4][8][4];
#pragma unroll
    for (int i = 0; i < 4; i++)
#pragma unroll
        for (int j = 0; j < 8; j++)
#pragma unroll
            for (int r = 0; r < 4; r++) acc[i][j][r] = 0.f;

    const int lrow = lane & 15;
    const int lcol = (lane >> 4) << 4;   // 0 or 16 bytes
    const uint32_t arow = (uint32_t)((wm * 64 + lrow) * 128);
    const uint32_t brow = (uint32_t)((wn * 64 + lrow) * 128);

    for (int k = 0; k < NCHUNK; k++) {
        const int s = k & (STAGES - 1);
        mbar_wait(mb_full + 8 * s, (k >> 2) & 1);
        const uint32_t a0 = sbase + SOFF_S0 + s * STAGE_BYTES;
        const uint32_t b0 = a0 + A_BYTES;
#pragma unroll
        for (int kk = 0; kk < 4; kk++) {
            const uint32_t colb = kk * 32 + lcol;
            uint32_t af[4][4];
#pragma unroll
            for (int mi = 0; mi < 4; mi++)
                ldsm_x4(af[mi][0], af[mi][1], af[mi][2], af[mi][3],
                        a0 + swz(arow + mi * 2048 + colb));
            uint32_t bf[8][2];
#pragma unroll
            for (int g = 0; g < 4; g++) {
                uint32_t r0, r1, r2, r3;
                ldsm_x4(r0, r1, r2, r3, b0 + swz(brow + g * 2048 + colb));
                bf[g * 2 + 0][0] = r0; bf[g * 2 + 0][1] = r2;
                bf[g * 2 + 1][0] = r1; bf[g * 2 + 1][1] = r3;
            }
#pragma unroll
            for (int mi = 0; mi < 4; mi++)
#pragma unroll
                for (int ni = 0; ni < 8; ni++)
                    mma_bf16(acc[mi][ni], af[mi], bf[ni][0], bf[ni][1]);
        }
        if (lane == 0) mbar_arrive(mb_empty + 8 * s);
    }

    // Epilogue: sq = xn + yn - 2*dot; per-fragment min.
    const float* xs = (const float*)(smem + SOFF_XN);
    const float* ys = (const float*)(smem + SOFF_YN);
    float m = 3.4e38f;
#pragma unroll
    for (int mi = 0; mi < 4; mi++) {
        float x0 = xs[wm * 64 + mi * 16 + (lane >> 2)];
        float x1 = xs[wm * 64 + mi * 16 + (lane >> 2) + 8];
#pragma unroll
        for (int ni = 0; ni < 8; ni++) {
            float y0 = ys[wn * 64 + ni * 8 + (lane & 3) * 2];
            float y1 = ys[wn * 64 + ni * 8 + (lane & 3) * 2 + 1];
            m = fminf(m, fmaf(-2.0f, acc[mi][ni][0], x0 + y0));
            m = fminf(m, fmaf(-2.0f, acc[mi][ni][1], x0 + y1));
            m = fminf(m, fmaf(-2.0f, acc[mi][ni][2], x1 + y0));
            m = fminf(m, fmaf(-2.0f, acc[mi][ni][3], x1 + y1));
        }
    }
#pragma unroll
    for (int off = 16; off > 0; off >>= 1)
        m = fminf(m, __shfl_xor_sync(0xFFFFFFFFu, m, off));
    if (lane == 0) atomicMin(&g_min_bits, enc_f(m));
}

// ------------- kernel 2: finalize -------------
__global__ void finalize_kernel(float* __restrict__ out) {
    out[0] = sqrtf(fmaxf(dec_f(g_min_bits), 0.0f));
}

extern "C" void kernel_launch(void* const* d_in, const int* in_sizes, int n_in,
                              void* d_out, int out_size) {
    const float* x = (const float*)d_in[0];  // [1, P, 512] fp32
    const float* y = (const float*)d_in[1];  // [1, R, 512] fp32
    int P = in_sizes[0] / DIM;
    int R = in_sizes[1] / DIM;

    int rows = P + R;  // one warp per row
    prep_kernel<<<(rows * 32 + 255) / 256, 256>>>(x, y, P, R);

    cudaFuncSetAttribute(min_dist_mma_kernel,
                         cudaFuncAttributeMaxDynamicSharedMemorySize, SMEM_BYTES);
    dim3 grid(R / BN, P / BM);  // (256, 16) = 4096 CTAs
    min_dist_mma_kernel<<<grid, NTHREADS, SMEM_BYTES>>>(P, R);

    finalize_kernel<<<1, 1>>>((float*)d_out);
}

// round 9
// speedup vs baseline: 1.0251x; 1.0251x over previous
#include <cuda_runtime.h>
#include <cuda_bf16.h>
#include <math.h>
#include <stdint.h>

#define DIM 512
#define P_MAX 2048
#define R_MAX 65536
#define BM 128
#define BN 256
#define BK 64                 // bf16 elems per chunk = 128 bytes/row
#define NCHUNK (DIM / BK)     // 8
#define STAGES 3
#define NTHREADS 512
#define A_BYTES (BM * 128)    // 16384
#define B_BYTES (BN * 128)    // 32768
#define STAGE_BYTES (A_BYTES + B_BYTES)          // 49152
#define SOFF_XN (STAGES * STAGE_BYTES)           // 147456
#define SOFF_YN (SOFF_XN + BM * 4)
#define SMEM_BYTES (SOFF_YN + BN * 4)            // 148992 -> 1 CTA/SM, 16 warps

// Scratch (no allocations allowed)
__device__ __nv_bfloat16 g_A[P_MAX * DIM];   // 2 MB
__device__ __nv_bfloat16 g_B[R_MAX * DIM];   // 64 MB
__device__ float g_xn[P_MAX];
__device__ float g_yn[R_MAX];
__device__ unsigned int g_min_bits;

// ---------------- helpers ----------------
__device__ __forceinline__ unsigned int enc_f(float f) {
    unsigned int u = __float_as_uint(f);
    return (u & 0x80000000u) ? ~u : (u | 0x80000000u);
}
__device__ __forceinline__ float dec_f(unsigned int u) {
    return (u & 0x80000000u) ? __uint_as_float(u & 0x7FFFFFFFu)
                             : __uint_as_float(~u);
}
__device__ __forceinline__ uint32_t smem_u32(const void* p) {
    uint32_t a;
    asm("{ .reg .u64 t; cvta.to.shared.u64 t, %1; cvt.u32.u64 %0, t; }"
        : "=r"(a) : "l"(p));
    return a;
}
__device__ __forceinline__ void cp16(uint32_t dst, const void* src) {
    asm volatile("cp.async.cg.shared.global [%0], [%1], 16;"
                 :: "r"(dst), "l"(src) : "memory");
}
__device__ __forceinline__ uint32_t swz(uint32_t off) {
    return off ^ ((off >> 3) & 0x70);   // SW128 pattern on 128B rows
}
__device__ __forceinline__ void ldsm_x4(uint32_t& r0, uint32_t& r1,
                                        uint32_t& r2, uint32_t& r3,
                                        uint32_t addr) {
    asm volatile("ldmatrix.sync.aligned.m8n8.x4.shared.b16 {%0,%1,%2,%3}, [%4];"
                 : "=r"(r0), "=r"(r1), "=r"(r2), "=r"(r3) : "r"(addr));
}
__device__ __forceinline__ void mma_bf16(float* c, const uint32_t* a,
                                         uint32_t b0, uint32_t b1) {
    asm volatile(
        "mma.sync.aligned.m16n8k16.row.col.f32.bf16.bf16.f32 "
        "{%0,%1,%2,%3}, {%4,%5,%6,%7}, {%8,%9}, {%0,%1,%2,%3};"
        : "+f"(c[0]), "+f"(c[1]), "+f"(c[2]), "+f"(c[3])
        : "r"(a[0]), "r"(a[1]), "r"(a[2]), "r"(a[3]), "r"(b0), "r"(b1));
}

// Load one K-chunk (A:128x64, B:256x64 bf16) into SW128-swizzled SMEM.
// 3072 x 16B units over 512 threads = 6 cp.async each.
__device__ __forceinline__ void load_stage(uint32_t sbase, int s, int k0,
                                           int bm, int bn, int tid) {
    uint32_t a0 = sbase + s * STAGE_BYTES;
    uint32_t b0 = a0 + A_BYTES;
#pragma unroll
    for (int i = 0; i < 2; i++) {            // A: 1024 units
        int u = tid + i * 512;
        int row = u >> 3, c = u & 7;
        uint32_t sw = swz(row * 128 + c * 16);
        cp16(a0 + sw, g_A + (size_t)(bm + row) * DIM + k0 + c * 8);
    }
#pragma unroll
    for (int i = 0; i < 4; i++) {            // B: 2048 units
        int u = tid + i * 512;
        int row = u >> 3, c = u & 7;
        uint32_t sw = swz(row * 128 + c * 16);
        cp16(b0 + sw, g_B + (size_t)(bn + row) * DIM + k0 + c * 8);
    }
}

// ------------- kernel 0: convert to bf16, fp32 norms, reset min -------------
__global__ void prep_kernel(const float* __restrict__ x,
                            const float* __restrict__ y, int P, int R) {
    int warp = (blockIdx.x * blockDim.x + threadIdx.x) >> 5;
    int lane = threadIdx.x & 31;
    if (blockIdx.x == 0 && threadIdx.x == 0) g_min_bits = 0xFFFFFFFFu;
    if (warp >= P + R) return;
    const float4* src4;
    uint2* dst2;
    if (warp < P) {
        src4 = (const float4*)(x + (size_t)warp * DIM);
        dst2 = (uint2*)(g_A + (size_t)warp * DIM);
    } else {
        int r = warp - P;
        src4 = (const float4*)(y + (size_t)r * DIM);
        dst2 = (uint2*)(g_B + (size_t)r * DIM);
    }
    float acc = 0.f;
#pragma unroll
    for (int j = 0; j < 4; j++) {
        float4 v = src4[lane + j * 32];
        acc += v.x * v.x + v.y * v.y + v.z * v.z + v.w * v.w;
        __nv_bfloat162 lo = __floats2bfloat162_rn(v.x, v.y);
        __nv_bfloat162 hi = __floats2bfloat162_rn(v.z, v.w);
        uint2 u;
        u.x = *reinterpret_cast<unsigned int*>(&lo);
        u.y = *reinterpret_cast<unsigned int*>(&hi);
        dst2[lane + j * 32] = u;
    }
#pragma unroll
    for (int off = 16; off > 0; off >>= 1)
        acc += __shfl_xor_sync(0xFFFFFFFFu, acc, off);
    if (lane == 0) {
        if (warp < P) g_xn[warp] = acc;
        else          g_yn[warp - P] = acc;
    }
}

// ------------- kernel 1: bf16 mma.sync GEMM + min reduction -------------
// 128x256 CTA tile, 16 warps in 4(M) x 4(N), 32x64 per warp, 1 CTA/SM.
__global__ void __launch_bounds__(NTHREADS, 1)
min_dist_mma_kernel(int P, int R) {
    extern __shared__ char smem[];
    uint32_t sbase = smem_u32(smem);
    const int tid = threadIdx.x;
    const int lane = tid & 31;
    const int warp = tid >> 5;
    const int wm = warp & 3;          // 0..3 : M direction (32 rows each)
    const int wn = warp >> 2;         // 0..3 : N direction (64 cols each)
    const int bm = blockIdx.x * BM;   // bm fastest -> B tiles revisited within
    const int bn = blockIdx.y * BN;   //   adjacent waves (DRAM-once for B)

    // Stage norms in SMEM for the epilogue.
    if (tid < 128)                    ((float*)(smem + SOFF_XN))[tid] = g_xn[bm + tid];
    else if (tid < 128 + 256)         ((float*)(smem + SOFF_YN))[tid - 128] = g_yn[bn + tid - 128];

    float acc[2][8][4];
#pragma unroll
    for (int i = 0; i < 2; i++)
#pragma unroll
        for (int j = 0; j < 8; j++)
#pragma unroll
            for (int r = 0; r < 4; r++) acc[i][j][r] = 0.f;

    // Prologue: prefetch chunks 0,1.
    load_stage(sbase, 0, 0, bm, bn, tid);
    asm volatile("cp.async.commit_group;" ::: "memory");
    load_stage(sbase, 1, BK, bm, bn, tid);
    asm volatile("cp.async.commit_group;" ::: "memory");

    const int lrow = lane & 15;
    const int lcol = (lane >> 4) << 4;   // 0 or 16 bytes

    for (int k = 0; k < NCHUNK; k++) {
        const int s = k % STAGES;
        asm volatile("cp.async.wait_group 1;" ::: "memory");
        __syncthreads();
        if (k + 2 < NCHUNK)
            load_stage(sbase, (k + 2) % STAGES, (k + 2) * BK, bm, bn, tid);
        asm volatile("cp.async.commit_group;" ::: "memory");

        const uint32_t a0 = sbase + s * STAGE_BYTES;
        const uint32_t b0 = a0 + A_BYTES;
#pragma unroll
        for (int kk = 0; kk < 4; kk++) {          // 4 x k16 steps per chunk
            const int colb = kk * 32 + lcol;
            uint32_t af[2][4];
#pragma unroll
            for (int mi = 0; mi < 2; mi++) {
                int row = wm * 32 + mi * 16 + lrow;
                ldsm_x4(af[mi][0], af[mi][1], af[mi][2], af[mi][3],
                        a0 + swz(row * 128 + colb));
            }
            uint32_t bf[8][2];
#pragma unroll
            for (int ni2 = 0; ni2 < 4; ni2++) {   // each x4 covers 2 n8 tiles
                int row = wn * 64 + ni2 * 16 + lrow;
                uint32_t r0, r1, r2, r3;
                ldsm_x4(r0, r1, r2, r3, b0 + swz(row * 128 + colb));
                bf[ni2 * 2 + 0][0] = r0; bf[ni2 * 2 + 0][1] = r2;
                bf[ni2 * 2 + 1][0] = r1; bf[ni2 * 2 + 1][1] = r3;
            }
#pragma unroll
            for (int mi = 0; mi < 2; mi++)
#pragma unroll
                for (int ni = 0; ni < 8; ni++)
                    mma_bf16(acc[mi][ni], af[mi], bf[ni][0], bf[ni][1]);
        }
    }

    // Epilogue: sq = xn + yn - 2*dot; per-fragment min.
    const float* xs = (const float*)(smem + SOFF_XN);
    const float* ys = (const float*)(smem + SOFF_YN);
    float m = 3.4e38f;
#pragma unroll
    for (int mi = 0; mi < 2; mi++) {
        float x0 = xs[wm * 32 + mi * 16 + (lane >> 2)];
        float x1 = xs[wm * 32 + mi * 16 + (lane >> 2) + 8];
#pragma unroll
        for (int ni = 0; ni < 8; ni++) {
            float y0 = ys[wn * 64 + ni * 8 + (lane & 3) * 2];
            float y1 = ys[wn * 64 + ni * 8 + (lane & 3) * 2 + 1];
            m = fminf(m, fmaf(-2.0f, acc[mi][ni][0], x0 + y0));
            m = fminf(m, fmaf(-2.0f, acc[mi][ni][1], x0 + y1));
            m = fminf(m, fmaf(-2.0f, acc[mi][ni][2], x1 + y0));
            m = fminf(m, fmaf(-2.0f, acc[mi][ni][3], x1 + y1));
        }
    }
#pragma unroll
    for (int off = 16; off > 0; off >>= 1)
        m = fminf(m, __shfl_xor_sync(0xFFFFFFFFu, m, off));
    if (lane == 0) atomicMin(&g_min_bits, enc_f(m));
}

// ------------- kernel 2: finalize -------------
__global__ void finalize_kernel(float* __restrict__ out) {
    out[0] = sqrtf(fmaxf(dec_f(g_min_bits), 0.0f));
}

extern "C" void kernel_launch(void* const* d_in, const int* in_sizes, int n_in,
                              void* d_out, int out_size) {
    const float* x = (const float*)d_in[0];  // [1, P, 512] fp32
    const float* y = (const float*)d_in[1];  // [1, R, 512] fp32
    int P = in_sizes[0] / DIM;
    int R = in_sizes[1] / DIM;

    int rows = P + R;  // one warp per row
    prep_kernel<<<(rows * 32 + 255) / 256, 256>>>(x, y, P, R);

    cudaFuncSetAttribute(min_dist_mma_kernel,
                         cudaFuncAttributeMaxDynamicSharedMemorySize, SMEM_BYTES);
    dim3 grid(P / BM, R / BN);  // (16, 256): bm fastest for B-tile L2 reuse
    min_dist_mma_kernel<<<grid, NTHREADS, SMEM_BYTES>>>(P, R);

    finalize_kernel<<<1, 1>>>((float*)d_out);
}

// round 10
// speedup vs baseline: 1.1357x; 1.1078x over previous
#include <cuda_runtime.h>
#include <cuda_bf16.h>
#include <math.h>
#include <stdint.h>

#define DIM 512
#define P_MAX 2048
#define R_MAX 65536
#define BM 128
#define BN 128
#define BK 64                 // bf16 elems per chunk = 128 bytes/row
#define NCHUNK (DIM / BK)     // 8
#define STAGES 3
#define A_BYTES (BM * 128)    // 16384
#define B_BYTES (BN * 128)    // 16384
#define STAGE_BYTES (A_BYTES + B_BYTES)          // 32768
#define SOFF_XN (STAGES * STAGE_BYTES)           // 98304
#define SOFF_YN (SOFF_XN + BM * 4)
#define SOFF_RED (SOFF_YN + BN * 4)              // 8 floats warp partials
#define SMEM_BYTES (SOFF_RED + 32)               // 99360 -> 2 CTAs/SM

// Scratch (no allocations allowed)
__device__ __nv_bfloat16 g_A[P_MAX * DIM];   // 2 MB
__device__ __nv_bfloat16 g_B[R_MAX * DIM];   // 64 MB
__device__ float g_xn[P_MAX];
__device__ float g_yn[R_MAX];
__device__ unsigned int g_min_bits;

// ---------------- helpers ----------------
__device__ __forceinline__ unsigned int enc_f(float f) {
    unsigned int u = __float_as_uint(f);
    return (u & 0x80000000u) ? ~u : (u | 0x80000000u);
}
__device__ __forceinline__ float dec_f(unsigned int u) {
    return (u & 0x80000000u) ? __uint_as_float(u & 0x7FFFFFFFu)
                             : __uint_as_float(~u);
}
__device__ __forceinline__ uint32_t smem_u32(const void* p) {
    uint32_t a;
    asm("{ .reg .u64 t; cvta.to.shared.u64 t, %1; cvt.u32.u64 %0, t; }"
        : "=r"(a) : "l"(p));
    return a;
}
__device__ __forceinline__ void cp16(uint32_t dst, const void* src) {
    asm volatile("cp.async.cg.shared.global [%0], [%1], 16;"
                 :: "r"(dst), "l"(src) : "memory");
}
__device__ __forceinline__ uint32_t swz(uint32_t off) {
    return off ^ ((off >> 3) & 0x70);   // SW128 pattern on 128B rows
}
__device__ __forceinline__ void ldsm_x4(uint32_t& r0, uint32_t& r1,
                                        uint32_t& r2, uint32_t& r3,
                                        uint32_t addr) {
    asm volatile("ldmatrix.sync.aligned.m8n8.x4.shared.b16 {%0,%1,%2,%3}, [%4];"
                 : "=r"(r0), "=r"(r1), "=r"(r2), "=r"(r3) : "r"(addr));
}
__device__ __forceinline__ void mma_bf16(float* c, const uint32_t* a,
                                         uint32_t b0, uint32_t b1) {
    asm volatile(
        "mma.sync.aligned.m16n8k16.row.col.f32.bf16.bf16.f32 "
        "{%0,%1,%2,%3}, {%4,%5,%6,%7}, {%8,%9}, {%0,%1,%2,%3};"
        : "+f"(c[0]), "+f"(c[1]), "+f"(c[2]), "+f"(c[3])
        : "r"(a[0]), "r"(a[1]), "r"(a[2]), "r"(a[3]), "r"(b0), "r"(b1));
}

// Load one K-chunk (A:128x64, B:128x64 bf16) into SW128-swizzled SMEM.
// 2048 x 16B units over 256 threads = 8 cp.async each.
__device__ __forceinline__ void load_stage(uint32_t sbase, int s, int k0,
                                           int bm, int bn, int tid) {
    uint32_t a0 = sbase + s * STAGE_BYTES;
    uint32_t b0 = a0 + A_BYTES;
#pragma unroll
    for (int i = 0; i < 4; i++) {            // A: 1024 units
        int u = tid + i * 256;
        int row = u >> 3, c = u & 7;
        uint32_t sw = swz(row * 128 + c * 16);
        cp16(a0 + sw, g_A + (size_t)(bm + row) * DIM + k0 + c * 8);
    }
#pragma unroll
    for (int i = 0; i < 4; i++) {            // B: 1024 units
        int u = tid + i * 256;
        int row = u >> 3, c = u & 7;
        uint32_t sw = swz(row * 128 + c * 16);
        cp16(b0 + sw, g_B + (size_t)(bn + row) * DIM + k0 + c * 8);
    }
}

// ------------- kernel 0: convert to bf16, fp32 norms, reset min -------------
__global__ void prep_kernel(const float* __restrict__ x,
                            const float* __restrict__ y, int P, int R) {
    int warp = (blockIdx.x * blockDim.x + threadIdx.x) >> 5;
    int lane = threadIdx.x & 31;
    if (blockIdx.x == 0 && threadIdx.x == 0) g_min_bits = 0xFFFFFFFFu;
    if (warp >= P + R) return;
    const float4* src4;
    uint2* dst2;
    if (warp < P) {
        src4 = (const float4*)(x + (size_t)warp * DIM);
        dst2 = (uint2*)(g_A + (size_t)warp * DIM);
    } else {
        int r = warp - P;
        src4 = (const float4*)(y + (size_t)r * DIM);
        dst2 = (uint2*)(g_B + (size_t)r * DIM);
    }
    float acc = 0.f;
#pragma unroll
    for (int j = 0; j < 4; j++) {
        float4 v = src4[lane + j * 32];
        acc += v.x * v.x + v.y * v.y + v.z * v.z + v.w * v.w;
        __nv_bfloat162 lo = __floats2bfloat162_rn(v.x, v.y);
        __nv_bfloat162 hi = __floats2bfloat162_rn(v.z, v.w);
        uint2 u;
        u.x = *reinterpret_cast<unsigned int*>(&lo);
        u.y = *reinterpret_cast<unsigned int*>(&hi);
        dst2[lane + j * 32] = u;
    }
#pragma unroll
    for (int off = 16; off > 0; off >>= 1)
        acc += __shfl_xor_sync(0xFFFFFFFFu, acc, off);
    if (lane == 0) {
        if (warp < P) g_xn[warp] = acc;
        else          g_yn[warp - P] = acc;
    }
}

// ------------- kernel 1: bf16 mma.sync GEMM + min reduction -------------
// 128x128 CTA tile, 8 warps in 4(M) x 2(N), 32x64 per warp, 2 CTAs/SM.
// Co-resident CTAs are de-phased by rotating the K-chunk schedule: bit 0 of
// (bid>>2) differs between wave-paired CTAs (pair distance 148 = 4*37), so
// their barrier points interleave instead of locking step.
__global__ void __launch_bounds__(256, 2)
min_dist_mma_kernel(int P, int R) {
    extern __shared__ char smem[];
    uint32_t sbase = smem_u32(smem);
    const int tid = threadIdx.x;
    const int lane = tid & 31;
    const int warp = tid >> 5;
    const int wm = warp & 3;          // 0..3 : M direction (32 rows each)
    const int wn = warp >> 2;         // 0..1 : N direction (64 cols each)
    const int bm = blockIdx.y * BM;
    const int bn = blockIdx.x * BN;
    const int bid = blockIdx.x + blockIdx.y * gridDim.x;
    const int kstart = ((bid >> 2) & 1) * (NCHUNK / 2);   // 0 or 4

    // Stage norms in SMEM for the epilogue.
    if (tid < 128)       ((float*)(smem + SOFF_XN))[tid] = g_xn[bm + tid];
    else                 ((float*)(smem + SOFF_YN))[tid - 128] = g_yn[bn + tid - 128];

    float acc[2][8][4];
#pragma unroll
    for (int i = 0; i < 2; i++)
#pragma unroll
        for (int j = 0; j < 8; j++)
#pragma unroll
            for (int r = 0; r < 4; r++) acc[i][j][r] = 0.f;

    // Prologue: prefetch rotated chunks 0,1.
    load_stage(sbase, 0, ((0 + kstart) & (NCHUNK - 1)) * BK, bm, bn, tid);
    asm volatile("cp.async.commit_group;" ::: "memory");
    load_stage(sbase, 1, ((1 + kstart) & (NCHUNK - 1)) * BK, bm, bn, tid);
    asm volatile("cp.async.commit_group;" ::: "memory");

    const int lrow = lane & 15;
    const int lcol = (lane >> 4) << 4;   // 0 or 16 bytes

    for (int k = 0; k < NCHUNK; k++) {
        const int s = k % STAGES;
        asm volatile("cp.async.wait_group 1;" ::: "memory");
        __syncthreads();
        if (k + 2 < NCHUNK)
            load_stage(sbase, (k + 2) % STAGES,
                       ((k + 2 + kstart) & (NCHUNK - 1)) * BK, bm, bn, tid);
        asm volatile("cp.async.commit_group;" ::: "memory");

        const uint32_t a0 = sbase + s * STAGE_BYTES;
        const uint32_t b0 = a0 + A_BYTES;
#pragma unroll
        for (int kk = 0; kk < 4; kk++) {          // 4 x k16 steps per chunk
            const int colb = kk * 32 + lcol;
            uint32_t af[2][4];
#pragma unroll
            for (int mi = 0; mi < 2; mi++) {
                int row = wm * 32 + mi * 16 + lrow;
                ldsm_x4(af[mi][0], af[mi][1], af[mi][2], af[mi][3],
                        a0 + swz(row * 128 + colb));
            }
            uint32_t bf[8][2];
#pragma unroll
            for (int ni2 = 0; ni2 < 4; ni2++) {   // each x4 covers 2 n8 tiles
                int row = wn * 64 + ni2 * 16 + lrow;
                uint32_t r0, r1, r2, r3;
                ldsm_x4(r0, r1, r2, r3, b0 + swz(row * 128 + colb));
                bf[ni2 * 2 + 0][0] = r0; bf[ni2 * 2 + 0][1] = r2;
                bf[ni2 * 2 + 1][0] = r1; bf[ni2 * 2 + 1][1] = r3;
            }
#pragma unroll
            for (int mi = 0; mi < 2; mi++)
#pragma unroll
                for (int ni = 0; ni < 8; ni++)
                    mma_bf16(acc[mi][ni], af[mi], bf[ni][0], bf[ni][1]);
        }
    }

    // Epilogue: sq = xn + yn - 2*dot; per-fragment min.
    const float* xs = (const float*)(smem + SOFF_XN);
    const float* ys = (const float*)(smem + SOFF_YN);
    float m = 3.4e38f;
#pragma unroll
    for (int mi = 0; mi < 2; mi++) {
        float x0 = xs[wm * 32 + mi * 16 + (lane >> 2)];
        float x1 = xs[wm * 32 + mi * 16 + (lane >> 2) + 8];
#pragma unroll
        for (int ni = 0; ni < 8; ni++) {
            float y0 = ys[wn * 64 + ni * 8 + (lane & 3) * 2];
            float y1 = ys[wn * 64 + ni * 8 + (lane & 3) * 2 + 1];
            m = fminf(m, fmaf(-2.0f, acc[mi][ni][0], x0 + y0));
            m = fminf(m, fmaf(-2.0f, acc[mi][ni][1], x0 + y1));
            m = fminf(m, fmaf(-2.0f, acc[mi][ni][2], x1 + y0));
            m = fminf(m, fmaf(-2.0f, acc[mi][ni][3], x1 + y1));
        }
    }
#pragma unroll
    for (int off = 16; off > 0; off >>= 1)
        m = fminf(m, __shfl_xor_sync(0xFFFFFFFFu, m, off));

    // Block-level min: 8 warp partials -> 1 atomic per CTA.
    float* red = (float*)(smem + SOFF_RED);
    if (lane == 0) red[warp] = m;
    __syncthreads();
    if (tid == 0) {
        float bm_ = red[0];
#pragma unroll
        for (int w = 1; w < 8; w++) bm_ = fminf(bm_, red[w]);
        atomicMin(&g_min_bits, enc_f(bm_));
    }
}

// ------------- kernel 2: finalize -------------
__global__ void finalize_kernel(float* __restrict__ out) {
    out[0] = sqrtf(fmaxf(dec_f(g_min_bits), 0.0f));
}

extern "C" void kernel_launch(void* const* d_in, const int* in_sizes, int n_in,
                              void* d_out, int out_size) {
    const float* x = (const float*)d_in[0];  // [1, P, 512] fp32
    const float* y = (const float*)d_in[1];  // [1, R, 512] fp32
    int P = in_sizes[0] / DIM;
    int R = in_sizes[1] / DIM;

    int rows = P + R;  // one warp per row
    prep_kernel<<<(rows * 32 + 255) / 256, 256>>>(x, y, P, R);

    cudaFuncSetAttribute(min_dist_mma_kernel,
                         cudaFuncAttributeMaxDynamicSharedMemorySize, SMEM_BYTES);
    dim3 grid(R / BN, P / BM);  // (512, 16) = 8192 CTAs
    min_dist_mma_kernel<<<grid, 256, SMEM_BYTES>>>(P, R);

    finalize_kernel<<<1, 1>>>((float*)d_out);
}